// round 13
// baseline (speedup 1.0000x reference)
#include <cuda_runtime.h>
#include <cstdint>

#define B_ 16
#define S_ 2048
#define E_ 768
#define H_ 96
#define M_ (B_*S_)

// Scratch: q (pre-scaled, tf32-rounded), k, v (tf32-rounded, row-major)
__device__ float g_q[M_*H_];
__device__ float g_k[M_*H_];
__device__ float g_v[M_*H_];

#define SCALE_ 0.1020620726159658f   // 96^-0.5

__device__ __forceinline__ float to_tf32(float x)
{
    asm("cvt.rna.tf32.f32 %0, %1;" : "=f"(x) : "f"(x));
    return x;
}

__device__ __forceinline__ void mma8(float c[4],
                                     uint32_t a0, uint32_t a1, uint32_t a2, uint32_t a3,
                                     uint32_t b0, uint32_t b1)
{
    asm volatile(
        "mma.sync.aligned.m16n8k8.row.col.f32.tf32.tf32.f32 "
        "{%0,%1,%2,%3}, {%4,%5,%6,%7}, {%8,%9}, {%0,%1,%2,%3};\n"
        : "+f"(c[0]), "+f"(c[1]), "+f"(c[2]), "+f"(c[3])
        : "r"(a0), "r"(a1), "r"(a2), "r"(a3), "r"(b0), "r"(b1));
}

__device__ __forceinline__ void cpa16(uint32_t dst, const float* src)
{
    asm volatile("cp.async.cg.shared.global [%0], [%1], 16;\n" :: "r"(dst), "l"(src) : "memory");
}
__device__ __forceinline__ void cpa_commit() { asm volatile("cp.async.commit_group;\n" ::: "memory"); }
__device__ __forceinline__ void cpa_wait1()  { asm volatile("cp.async.wait_group 1;\n" ::: "memory"); }

// ----------------------------- QKV projection -----------------------------
// C[32768,96] = X @ W. 128 threads = 4 warps, warp = 32 rows x 96 cols.
// cp.async double-buffer, ordering identical to the proven attn skeleton.
#define XLD 36
#define WLD 104
#define QSTAGEF (128*XLD + 32*WLD)        // 7936 floats
#define QKV_SMEM_BYTES (2*QSTAGEF*4)      // 63488 B

__device__ __forceinline__ void qkv_fill(const float* __restrict__ X,
                                         const float* __restrict__ W,
                                         int row0, int kt, uint32_t st_u, int tid)
{
    uint32_t xs_u = st_u;
    uint32_t ws_u = st_u + (uint32_t)(128*XLD)*4;
    #pragma unroll
    for (int i = 0; i < 8; i++) {           // X: 128 rows x 8 float4 = 1024
        int idx = tid + i*128;
        int r = idx >> 3, c = idx & 7;
        cpa16(xs_u + (uint32_t)(r*XLD + c*4)*4,
              &X[(size_t)(row0 + r)*E_ + kt*32 + c*4]);
    }
    #pragma unroll
    for (int i = 0; i < 6; i++) {           // W: 32 rows x 24 float4 = 768  (FIXED)
        int idx = tid + i*128;
        int r = idx / 24, c = idx - r*24;   // r: 0..31, c: 0..23
        cpa16(ws_u + (uint32_t)(r*WLD + c*4)*4,
              &W[(size_t)(kt*32 + r)*H_ + c*4]);
    }
}

__global__ __launch_bounds__(128, 3) void qkv_kernel(
    const float* __restrict__ X,
    const float* __restrict__ Wq,
    const float* __restrict__ Wk,
    const float* __restrict__ Wv)
{
    extern __shared__ float qs[];
    const int tid  = threadIdx.x;
    const int w    = tid >> 5;
    const int lane = tid & 31;
    const int g    = lane >> 2;
    const int t    = lane & 3;
    const int row0 = blockIdx.x * 128;
    const int y    = blockIdx.y;

    const float* W = (y == 0) ? Wq : (y == 1) ? Wk : Wv;
    float* Out     = (y == 0) ? g_q : (y == 1) ? g_k : g_v;
    const float sc = (y == 0) ? SCALE_ : 1.0f;

    const uint32_t smem_u = (uint32_t)__cvta_generic_to_shared(qs);

    float o[2][12][4];
    #pragma unroll
    for (int r = 0; r < 2; r++)
        #pragma unroll
        for (int n = 0; n < 12; n++)
            o[r][n][0] = o[r][n][1] = o[r][n][2] = o[r][n][3] = 0.0f;

    // prologue: prefetch chunk 0
    qkv_fill(X, W, row0, 0, smem_u, tid);
    cpa_commit();

    for (int kt = 0; kt < 24; kt++) {
        if (kt + 1 < 24)
            qkv_fill(X, W, row0, kt + 1, smem_u + (uint32_t)(((kt+1)&1)*QSTAGEF)*4, tid);
        cpa_commit();
        cpa_wait1();
        __syncthreads();

        const float* Xs = qs + (kt & 1)*QSTAGEF;
        const float* Ws = Xs + 128*XLD;

        #pragma unroll
        for (int kc = 0; kc < 4; kc++) {
            uint32_t a[2][4];
            #pragma unroll
            for (int rt = 0; rt < 2; rt++) {
                int rr = w*32 + rt*16 + g;
                a[rt][0] = __float_as_uint(to_tf32(Xs[rr*XLD + kc*8 + t]));
                a[rt][1] = __float_as_uint(to_tf32(Xs[(rr+8)*XLD + kc*8 + t]));
                a[rt][2] = __float_as_uint(to_tf32(Xs[rr*XLD + kc*8 + t + 4]));
                a[rt][3] = __float_as_uint(to_tf32(Xs[(rr+8)*XLD + kc*8 + t + 4]));
            }
            #pragma unroll
            for (int n = 0; n < 12; n++) {
                uint32_t b0 = __float_as_uint(to_tf32(Ws[(kc*8 + t)*WLD + n*8 + g]));
                uint32_t b1 = __float_as_uint(to_tf32(Ws[(kc*8 + t + 4)*WLD + n*8 + g]));
                mma8(o[0][n], a[0][0],a[0][1],a[0][2],a[0][3], b0,b1);
                mma8(o[1][n], a[1][0],a[1][1],a[1][2],a[1][3], b0,b1);
            }
        }
        __syncthreads();
    }

    // epilogue: tf32-round (Q also pre-scaled) so attn can consume directly
    #pragma unroll
    for (int rt = 0; rt < 2; rt++) {
        int rr = row0 + w*32 + rt*16 + g;
        #pragma unroll
        for (int n = 0; n < 12; n++) {
            float2 lo = make_float2(to_tf32(o[rt][n][0]*sc), to_tf32(o[rt][n][1]*sc));
            float2 hi = make_float2(to_tf32(o[rt][n][2]*sc), to_tf32(o[rt][n][3]*sc));
            *reinterpret_cast<float2*>(&Out[(size_t)rr*H_ + n*8 + 2*t]) = lo;
            *reinterpret_cast<float2*>(&Out[(size_t)(rr+8)*H_ + n*8 + 2*t]) = hi;
        }
    }
}

// ----------------------------- Attention -----------------------------
// R10 body unchanged; __launch_bounds__(256, 2) caps regs at 128 so two CTAs
// fit the 64K-reg SM file (occupancy 12.5% -> 25%, 4 warps/SMSP).
#define KLD 100
#define VLD 104
#define STAGEF (64*KLD + 64*VLD)          // 13056 floats
#define ATTN_SMEM_BYTES (2*STAGEF*4)      // 104448 B

__device__ __forceinline__ void attn_fill(int b, int kt, uint32_t st_u, int tid)
{
    uint32_t ks_u = st_u;
    uint32_t vs_u = st_u + (uint32_t)(64*KLD)*4;
    #pragma unroll
    for (int i = 0; i < 6; i++) {           // 64 rows x 24 float4 = 1536
        int idx = tid + i*256;
        int r = idx / 24, c = idx - r*24;
        size_t gb = (size_t)(b*S_ + kt*64 + r)*H_ + c*4;
        cpa16(ks_u + (uint32_t)(r*KLD + c*4)*4, &g_k[gb]);
        cpa16(vs_u + (uint32_t)(r*VLD + c*4)*4, &g_v[gb]);
    }
}

__global__ __launch_bounds__(256, 2) void attn_kernel(float* __restrict__ out)
{
    extern __shared__ float smem[];
    const int tid  = threadIdx.x;
    const int w    = tid >> 5;
    const int lane = tid & 31;
    const int g    = lane >> 2;
    const int t    = lane & 3;
    const int qt   = (S_/128 - 1) - blockIdx.x;   // big CTAs first
    const int b    = blockIdx.y;
    const int rq0  = b*S_ + qt*128;

    const uint32_t smem_u = (uint32_t)__cvta_generic_to_shared(smem);

    // Q fragments straight from gmem (pre-scaled, pre-rounded, L2-resident)
    uint32_t qa[12][4];
    {
        const size_t qr0 = (size_t)(rq0 + w*16 + g)*H_;
        const size_t qr8 = qr0 + 8*H_;
        #pragma unroll
        for (int kc = 0; kc < 12; kc++) {
            qa[kc][0] = __float_as_uint(g_q[qr0 + kc*8 + t]);
            qa[kc][1] = __float_as_uint(g_q[qr8 + kc*8 + t]);
            qa[kc][2] = __float_as_uint(g_q[qr0 + kc*8 + t + 4]);
            qa[kc][3] = __float_as_uint(g_q[qr8 + kc*8 + t + 4]);
        }
    }

    float o[12][4];
    #pragma unroll
    for (int n = 0; n < 12; n++)
        o[n][0] = o[n][1] = o[n][2] = o[n][3] = 0.0f;

    float m_lo = -1e30f, m_hi = -1e30f, l_lo = 0.0f, l_hi = 0.0f;
    const int rlo = qt*128 + w*16 + g;
    const int rhi = rlo + 8;
    const int nkt = 2*qt + 2;

    // prologue: prefetch tile 0
    attn_fill(b, 0, smem_u, tid);
    cpa_commit();

    for (int kt = 0; kt < nkt; kt++) {
        if (kt + 1 < nkt)
            attn_fill(b, kt + 1, smem_u + (uint32_t)(((kt+1)&1)*STAGEF)*4, tid);
        cpa_commit();
        cpa_wait1();
        __syncthreads();

        const float* Ks = smem + (kt & 1)*STAGEF;
        const float* Vs = Ks + 64*KLD;

        // ---- S = Qscaled @ K^T ----
        float s[8][4];
        #pragma unroll
        for (int j = 0; j < 8; j++) {
            s[j][0]=s[j][1]=s[j][2]=s[j][3]=0.0f;
            #pragma unroll
            for (int kc = 0; kc < 12; kc++) {
                uint32_t b0 = __float_as_uint(Ks[(j*8+g)*KLD + kc*8 + t]);
                uint32_t b1 = __float_as_uint(Ks[(j*8+g)*KLD + kc*8 + t + 4]);
                mma8(s[j], qa[kc][0],qa[kc][1],qa[kc][2],qa[kc][3], b0,b1);
            }
        }

        // ---- causal mask (near diagonal only) ----
        if (kt*64 + 63 > rlo) {
            #pragma unroll
            for (int j = 0; j < 8; j++) {
                int c0 = kt*64 + j*8 + 2*t;
                if (c0     > rlo) s[j][0] = -1e30f;
                if (c0 + 1 > rlo) s[j][1] = -1e30f;
                if (c0     > rhi) s[j][2] = -1e30f;
                if (c0 + 1 > rhi) s[j][3] = -1e30f;
            }
        }

        // ---- online softmax in registers ----
        float pm_lo = -1e30f, pm_hi = -1e30f;
        #pragma unroll
        for (int j = 0; j < 8; j++) {
            pm_lo = fmaxf(pm_lo, fmaxf(s[j][0], s[j][1]));
            pm_hi = fmaxf(pm_hi, fmaxf(s[j][2], s[j][3]));
        }
        pm_lo = fmaxf(pm_lo, __shfl_xor_sync(0xffffffffu, pm_lo, 1));
        pm_lo = fmaxf(pm_lo, __shfl_xor_sync(0xffffffffu, pm_lo, 2));
        pm_hi = fmaxf(pm_hi, __shfl_xor_sync(0xffffffffu, pm_hi, 1));
        pm_hi = fmaxf(pm_hi, __shfl_xor_sync(0xffffffffu, pm_hi, 2));

        float mlo_n = fmaxf(m_lo, pm_lo);
        float mhi_n = fmaxf(m_hi, pm_hi);
        float flo = __expf(m_lo - mlo_n);
        float fhi = __expf(m_hi - mhi_n);
        m_lo = mlo_n; m_hi = mhi_n;

        float slo = 0.0f, shi = 0.0f;
        #pragma unroll
        for (int j = 0; j < 8; j++) {
            s[j][0] = __expf(s[j][0] - mlo_n); slo += s[j][0];
            s[j][1] = __expf(s[j][1] - mlo_n); slo += s[j][1];
            s[j][2] = __expf(s[j][2] - mhi_n); shi += s[j][2];
            s[j][3] = __expf(s[j][3] - mhi_n); shi += s[j][3];
        }
        slo += __shfl_xor_sync(0xffffffffu, slo, 1);
        slo += __shfl_xor_sync(0xffffffffu, slo, 2);
        shi += __shfl_xor_sync(0xffffffffu, shi, 1);
        shi += __shfl_xor_sync(0xffffffffu, shi, 2);
        l_lo = l_lo*flo + slo;
        l_hi = l_hi*fhi + shi;

        #pragma unroll
        for (int n = 0; n < 12; n++) {
            o[n][0]*=flo; o[n][1]*=flo; o[n][2]*=fhi; o[n][3]*=fhi;
        }

        // ---- round P to tf32 (rna) ----
        #pragma unroll
        for (int j = 0; j < 8; j++) {
            s[j][0] = to_tf32(s[j][0]);
            s[j][1] = to_tf32(s[j][1]);
            s[j][2] = to_tf32(s[j][2]);
            s[j][3] = to_tf32(s[j][3]);
        }

        // ---- O += P @ V : P accum->A frags via shfl ----
        const int src = (g << 2) + (t >> 1);
        #pragma unroll
        for (int j = 0; j < 8; j++) {
            float v0 = __shfl_sync(0xffffffffu, s[j][0], src);
            float v1 = __shfl_sync(0xffffffffu, s[j][1], src);
            float v2 = __shfl_sync(0xffffffffu, s[j][2], src);
            float v3 = __shfl_sync(0xffffffffu, s[j][3], src);
            float u0 = __shfl_sync(0xffffffffu, s[j][0], src + 2);
            float u1 = __shfl_sync(0xffffffffu, s[j][1], src + 2);
            float u2 = __shfl_sync(0xffffffffu, s[j][2], src + 2);
            float u3 = __shfl_sync(0xffffffffu, s[j][3], src + 2);
            bool odd = (t & 1);
            uint32_t pa0 = __float_as_uint(odd ? v1 : v0);
            uint32_t pa1 = __float_as_uint(odd ? v3 : v2);
            uint32_t pa2 = __float_as_uint(odd ? u1 : u0);
            uint32_t pa3 = __float_as_uint(odd ? u3 : u2);
            #pragma unroll
            for (int n = 0; n < 12; n++) {
                uint32_t b0 = __float_as_uint(Vs[(j*8 + t)*VLD + n*8 + g]);
                uint32_t b1 = __float_as_uint(Vs[(j*8 + t + 4)*VLD + n*8 + g]);
                mma8(o[n], pa0,pa1,pa2,pa3, b0,b1);
            }
        }
        __syncthreads();   // all reads of this buffer done before next fill overwrites it
    }

    // ---- normalize and store ----
    const float ilo = 1.0f / l_lo;
    const float ihi = 1.0f / l_hi;
    const int orow = rq0 + w*16 + g;
    #pragma unroll
    for (int n = 0; n < 12; n++) {
        float2 lo = make_float2(o[n][0]*ilo, o[n][1]*ilo);
        float2 hi = make_float2(o[n][2]*ihi, o[n][3]*ihi);
        *reinterpret_cast<float2*>(&out[(size_t)orow*H_ + n*8 + 2*t]) = lo;
        *reinterpret_cast<float2*>(&out[(size_t)(orow+8)*H_ + n*8 + 2*t]) = hi;
    }
}

// ----------------------------- Launch -----------------------------
extern "C" void kernel_launch(void* const* d_in, const int* in_sizes, int n_in,
                              void* d_out, int out_size)
{
    const float* x  = (const float*)d_in[0];
    const float* Wq = (const float*)d_in[1];
    const float* Wk = (const float*)d_in[2];
    const float* Wv = (const float*)d_in[3];
    float* out = (float*)d_out;

    cudaFuncSetAttribute(qkv_kernel, cudaFuncAttributeMaxDynamicSharedMemorySize,
                         QKV_SMEM_BYTES);
    cudaFuncSetAttribute(attn_kernel, cudaFuncAttributeMaxDynamicSharedMemorySize,
                         ATTN_SMEM_BYTES);

    dim3 g1(M_/128, 3);
    qkv_kernel<<<g1, 128, QKV_SMEM_BYTES>>>(x, Wq, Wk, Wv);

    dim3 g2(S_/128, B_);
    attn_kernel<<<g2, 256, ATTN_SMEM_BYTES>>>(out);
}

// round 15
// speedup vs baseline: 1.2601x; 1.2601x over previous
#include <cuda_runtime.h>
#include <cstdint>

#define B_ 16
#define S_ 2048
#define E_ 768
#define H_ 96
#define M_ (B_*S_)

// Scratch: q (pre-scaled, tf32-rounded), k, v (tf32-rounded, row-major)
__device__ float g_q[M_*H_];
__device__ float g_k[M_*H_];
__device__ float g_v[M_*H_];

#define SCALE_ 0.1020620726159658f   // 96^-0.5

__device__ __forceinline__ float to_tf32(float x)
{
    asm("cvt.rna.tf32.f32 %0, %1;" : "=f"(x) : "f"(x));
    return x;
}

__device__ __forceinline__ void mma8(float c[4],
                                     uint32_t a0, uint32_t a1, uint32_t a2, uint32_t a3,
                                     uint32_t b0, uint32_t b1)
{
    asm volatile(
        "mma.sync.aligned.m16n8k8.row.col.f32.tf32.tf32.f32 "
        "{%0,%1,%2,%3}, {%4,%5,%6,%7}, {%8,%9}, {%0,%1,%2,%3};\n"
        : "+f"(c[0]), "+f"(c[1]), "+f"(c[2]), "+f"(c[3])
        : "r"(a0), "r"(a1), "r"(a2), "r"(a3), "r"(b0), "r"(b1));
}

__device__ __forceinline__ void cpa16(uint32_t dst, const float* src)
{
    asm volatile("cp.async.cg.shared.global [%0], [%1], 16;\n" :: "r"(dst), "l"(src) : "memory");
}
__device__ __forceinline__ void cpa_commit() { asm volatile("cp.async.commit_group;\n" ::: "memory"); }
__device__ __forceinline__ void cpa_wait1()  { asm volatile("cp.async.wait_group 1;\n" ::: "memory"); }

// ----------------------------- QKV projection -----------------------------
// Unchanged from R13 (passing). 128 threads = 4 warps, warp = 32 rows x 96 cols.
#define XLD 36
#define WLD 104
#define QSTAGEF (128*XLD + 32*WLD)        // 7936 floats
#define QKV_SMEM_BYTES (2*QSTAGEF*4)      // 63488 B

__device__ __forceinline__ void qkv_fill(const float* __restrict__ X,
                                         const float* __restrict__ W,
                                         int row0, int kt, uint32_t st_u, int tid)
{
    uint32_t xs_u = st_u;
    uint32_t ws_u = st_u + (uint32_t)(128*XLD)*4;
    #pragma unroll
    for (int i = 0; i < 8; i++) {           // X: 128 rows x 8 float4 = 1024
        int idx = tid + i*128;
        int r = idx >> 3, c = idx & 7;
        cpa16(xs_u + (uint32_t)(r*XLD + c*4)*4,
              &X[(size_t)(row0 + r)*E_ + kt*32 + c*4]);
    }
    #pragma unroll
    for (int i = 0; i < 6; i++) {           // W: 32 rows x 24 float4 = 768
        int idx = tid + i*128;
        int r = idx / 24, c = idx - r*24;
        cpa16(ws_u + (uint32_t)(r*WLD + c*4)*4,
              &W[(size_t)(kt*32 + r)*H_ + c*4]);
    }
}

__global__ __launch_bounds__(128, 3) void qkv_kernel(
    const float* __restrict__ X,
    const float* __restrict__ Wq,
    const float* __restrict__ Wk,
    const float* __restrict__ Wv)
{
    extern __shared__ float qs[];
    const int tid  = threadIdx.x;
    const int w    = tid >> 5;
    const int lane = tid & 31;
    const int g    = lane >> 2;
    const int t    = lane & 3;
    const int row0 = blockIdx.x * 128;
    const int y    = blockIdx.y;

    const float* W = (y == 0) ? Wq : (y == 1) ? Wk : Wv;
    float* Out     = (y == 0) ? g_q : (y == 1) ? g_k : g_v;
    const float sc = (y == 0) ? SCALE_ : 1.0f;

    const uint32_t smem_u = (uint32_t)__cvta_generic_to_shared(qs);

    float o[2][12][4];
    #pragma unroll
    for (int r = 0; r < 2; r++)
        #pragma unroll
        for (int n = 0; n < 12; n++)
            o[r][n][0] = o[r][n][1] = o[r][n][2] = o[r][n][3] = 0.0f;

    qkv_fill(X, W, row0, 0, smem_u, tid);
    cpa_commit();

    for (int kt = 0; kt < 24; kt++) {
        if (kt + 1 < 24)
            qkv_fill(X, W, row0, kt + 1, smem_u + (uint32_t)(((kt+1)&1)*QSTAGEF)*4, tid);
        cpa_commit();
        cpa_wait1();
        __syncthreads();

        const float* Xs = qs + (kt & 1)*QSTAGEF;
        const float* Ws = Xs + 128*XLD;

        #pragma unroll
        for (int kc = 0; kc < 4; kc++) {
            uint32_t a[2][4];
            #pragma unroll
            for (int rt = 0; rt < 2; rt++) {
                int rr = w*32 + rt*16 + g;
                a[rt][0] = __float_as_uint(to_tf32(Xs[rr*XLD + kc*8 + t]));
                a[rt][1] = __float_as_uint(to_tf32(Xs[(rr+8)*XLD + kc*8 + t]));
                a[rt][2] = __float_as_uint(to_tf32(Xs[rr*XLD + kc*8 + t + 4]));
                a[rt][3] = __float_as_uint(to_tf32(Xs[(rr+8)*XLD + kc*8 + t + 4]));
            }
            #pragma unroll
            for (int n = 0; n < 12; n++) {
                uint32_t b0 = __float_as_uint(to_tf32(Ws[(kc*8 + t)*WLD + n*8 + g]));
                uint32_t b1 = __float_as_uint(to_tf32(Ws[(kc*8 + t + 4)*WLD + n*8 + g]));
                mma8(o[0][n], a[0][0],a[0][1],a[0][2],a[0][3], b0,b1);
                mma8(o[1][n], a[1][0],a[1][1],a[1][2],a[1][3], b0,b1);
            }
        }
        __syncthreads();
    }

    #pragma unroll
    for (int rt = 0; rt < 2; rt++) {
        int rr = row0 + w*32 + rt*16 + g;
        #pragma unroll
        for (int n = 0; n < 12; n++) {
            float2 lo = make_float2(to_tf32(o[rt][n][0]*sc), to_tf32(o[rt][n][1]*sc));
            float2 hi = make_float2(to_tf32(o[rt][n][2]*sc), to_tf32(o[rt][n][3]*sc));
            *reinterpret_cast<float2*>(&Out[(size_t)rr*H_ + n*8 + 2*t]) = lo;
            *reinterpret_cast<float2*>(&Out[(size_t)(rr+8)*H_ + n*8 + 2*t]) = hi;
        }
    }
}

// ----------------------------- Attention -----------------------------
// Cross-tile pipelined flash: PV(kt-1) + O-rescale overlap softmax(kt).
// 3-stage cp.async ring so V(kt-1) survives fill(kt+1). Natural regs (no cap).
#define KLD 100
#define VLD 104
#define STAGEF (64*KLD + 64*VLD)          // 13056 floats
#define ATTN_SMEM_BYTES (3*STAGEF*4)      // 156672 B

__device__ __forceinline__ void attn_fill(int b, int kt, uint32_t st_u, int tid)
{
    uint32_t ks_u = st_u;
    uint32_t vs_u = st_u + (uint32_t)(64*KLD)*4;
    #pragma unroll
    for (int i = 0; i < 6; i++) {           // 64 rows x 24 float4 = 1536
        int idx = tid + i*256;
        int r = idx / 24, c = idx - r*24;
        size_t gb = (size_t)(b*S_ + kt*64 + r)*H_ + c*4;
        cpa16(ks_u + (uint32_t)(r*KLD + c*4)*4, &g_k[gb]);
        cpa16(vs_u + (uint32_t)(r*VLD + c*4)*4, &g_v[gb]);
    }
}

// P accum-layout -> A-fragment layout via shfl (proven in R6/R10)
__device__ __forceinline__ void p_to_afrag(const float s[4], uint32_t pa[4],
                                           int src, bool odd)
{
    float v0 = __shfl_sync(0xffffffffu, s[0], src);
    float v1 = __shfl_sync(0xffffffffu, s[1], src);
    float v2 = __shfl_sync(0xffffffffu, s[2], src);
    float v3 = __shfl_sync(0xffffffffu, s[3], src);
    float u0 = __shfl_sync(0xffffffffu, s[0], src + 2);
    float u1 = __shfl_sync(0xffffffffu, s[1], src + 2);
    float u2 = __shfl_sync(0xffffffffu, s[2], src + 2);
    float u3 = __shfl_sync(0xffffffffu, s[3], src + 2);
    pa[0] = __float_as_uint(odd ? v1 : v0);
    pa[1] = __float_as_uint(odd ? v3 : v2);
    pa[2] = __float_as_uint(odd ? u1 : u0);
    pa[3] = __float_as_uint(odd ? u3 : u2);
}

__global__ __launch_bounds__(256) void attn_kernel(float* __restrict__ out)
{
    extern __shared__ float smem[];
    const int tid  = threadIdx.x;
    const int w    = tid >> 5;
    const int lane = tid & 31;
    const int g    = lane >> 2;
    const int t    = lane & 3;
    const int qt   = (S_/128 - 1) - blockIdx.x;   // big CTAs first
    const int b    = blockIdx.y;
    const int rq0  = b*S_ + qt*128;

    const uint32_t smem_u = (uint32_t)__cvta_generic_to_shared(smem);

    // Zero V region of stage 2 (read by the branchless kt=0 pipelined PV)
    {
        float* vz = smem + 2*STAGEF + 64*KLD;
        for (int i = tid; i < 64*VLD; i += 256) vz[i] = 0.0f;
    }

    // Q fragments straight from gmem (pre-scaled, pre-rounded, L2-resident)
    uint32_t qa[12][4];
    {
        const size_t qr0 = (size_t)(rq0 + w*16 + g)*H_;
        const size_t qr8 = qr0 + 8*H_;
        #pragma unroll
        for (int kc = 0; kc < 12; kc++) {
            qa[kc][0] = __float_as_uint(g_q[qr0 + kc*8 + t]);
            qa[kc][1] = __float_as_uint(g_q[qr8 + kc*8 + t]);
            qa[kc][2] = __float_as_uint(g_q[qr0 + kc*8 + t + 4]);
            qa[kc][3] = __float_as_uint(g_q[qr8 + kc*8 + t + 4]);
        }
    }

    float o[12][4];
    uint32_t pa[8][4];
    #pragma unroll
    for (int n = 0; n < 12; n++)
        o[n][0] = o[n][1] = o[n][2] = o[n][3] = 0.0f;
    #pragma unroll
    for (int j = 0; j < 8; j++)
        pa[j][0] = pa[j][1] = pa[j][2] = pa[j][3] = 0;   // 0.0f bit pattern

    float m_lo = -1e30f, m_hi = -1e30f, l_lo = 0.0f, l_hi = 0.0f;
    float fp_lo = 1.0f, fp_hi = 1.0f;     // saved rescale factors of prev tile
    const int rlo = qt*128 + w*16 + g;
    const int rhi = rlo + 8;
    const int nkt = 2*qt + 2;
    const int src = (g << 2) + (t >> 1);
    const bool odd = (t & 1);

    attn_fill(b, 0, smem_u, tid);
    cpa_commit();

    for (int kt = 0; kt < nkt; kt++) {
        if (kt + 1 < nkt)
            attn_fill(b, kt + 1, smem_u + (uint32_t)(((kt+1)%3)*STAGEF)*4, tid);
        cpa_commit();
        cpa_wait1();
        __syncthreads();

        const float* Ks = smem + (kt % 3)*STAGEF;
        const float* Vp = smem + ((kt + 2) % 3)*STAGEF + 64*KLD;  // V of tile kt-1

        // ---- S = Qscaled @ K^T (current tile) ----
        float s[8][4];
        #pragma unroll
        for (int j = 0; j < 8; j++) {
            s[j][0]=s[j][1]=s[j][2]=s[j][3]=0.0f;
            #pragma unroll
            for (int kc = 0; kc < 12; kc++) {
                uint32_t b0 = __float_as_uint(Ks[(j*8+g)*KLD + kc*8 + t]);
                uint32_t b1 = __float_as_uint(Ks[(j*8+g)*KLD + kc*8 + t + 4]);
                mma8(s[j], qa[kc][0],qa[kc][1],qa[kc][2],qa[kc][3], b0,b1);
            }
        }

        // ---- causal mask (near diagonal only) ----
        if (kt*64 + 63 > rlo) {
            #pragma unroll
            for (int j = 0; j < 8; j++) {
                int c0 = kt*64 + j*8 + 2*t;
                if (c0     > rlo) s[j][0] = -1e30f;
                if (c0 + 1 > rlo) s[j][1] = -1e30f;
                if (c0     > rhi) s[j][2] = -1e30f;
                if (c0 + 1 > rhi) s[j][3] = -1e30f;
            }
        }

        // ---- row-max reduction (current tile) ----
        float pm_lo = -1e30f, pm_hi = -1e30f;
        #pragma unroll
        for (int j = 0; j < 8; j++) {
            pm_lo = fmaxf(pm_lo, fmaxf(s[j][0], s[j][1]));
            pm_hi = fmaxf(pm_hi, fmaxf(s[j][2], s[j][3]));
        }
        pm_lo = fmaxf(pm_lo, __shfl_xor_sync(0xffffffffu, pm_lo, 1));
        pm_lo = fmaxf(pm_lo, __shfl_xor_sync(0xffffffffu, pm_lo, 2));
        pm_hi = fmaxf(pm_hi, __shfl_xor_sync(0xffffffffu, pm_hi, 1));
        pm_hi = fmaxf(pm_hi, __shfl_xor_sync(0xffffffffu, pm_hi, 2));

        float mlo_n = fmaxf(m_lo, pm_lo);
        float mhi_n = fmaxf(m_hi, pm_hi);
        float flo = __expf(m_lo - mlo_n);
        float fhi = __expf(m_hi - mhi_n);
        m_lo = mlo_n; m_hi = mhi_n;

        // ---- PIPELINED O update for PREVIOUS tile (overlaps softmax below) ----
        #pragma unroll
        for (int n = 0; n < 12; n++) {
            o[n][0]*=fp_lo; o[n][1]*=fp_lo; o[n][2]*=fp_hi; o[n][3]*=fp_hi;
        }
        #pragma unroll
        for (int j = 0; j < 8; j++) {
            #pragma unroll
            for (int n = 0; n < 12; n++) {
                uint32_t b0 = __float_as_uint(Vp[(j*8 + t)*VLD + n*8 + g]);
                uint32_t b1 = __float_as_uint(Vp[(j*8 + t + 4)*VLD + n*8 + g]);
                mma8(o[n], pa[j][0],pa[j][1],pa[j][2],pa[j][3], b0,b1);
            }
        }

        // ---- exp + denominator (current tile) ----
        float slo = 0.0f, shi = 0.0f;
        #pragma unroll
        for (int j = 0; j < 8; j++) {
            s[j][0] = __expf(s[j][0] - mlo_n); slo += s[j][0];
            s[j][1] = __expf(s[j][1] - mlo_n); slo += s[j][1];
            s[j][2] = __expf(s[j][2] - mhi_n); shi += s[j][2];
            s[j][3] = __expf(s[j][3] - mhi_n); shi += s[j][3];
        }
        slo += __shfl_xor_sync(0xffffffffu, slo, 1);
        slo += __shfl_xor_sync(0xffffffffu, slo, 2);
        shi += __shfl_xor_sync(0xffffffffu, shi, 1);
        shi += __shfl_xor_sync(0xffffffffu, shi, 2);
        l_lo = l_lo*flo + slo;
        l_hi = l_hi*fhi + shi;

        // ---- round P to tf32 and convert to A-fragments for NEXT iteration ----
        #pragma unroll
        for (int j = 0; j < 8; j++) {
            s[j][0] = to_tf32(s[j][0]);
            s[j][1] = to_tf32(s[j][1]);
            s[j][2] = to_tf32(s[j][2]);
            s[j][3] = to_tf32(s[j][3]);
            p_to_afrag(s[j], pa[j], src, odd);
        }
        fp_lo = flo; fp_hi = fhi;

        __syncthreads();   // all reads of stages kt%3 and (kt-1)%3 done
    }

    // ---- epilogue: fold in the last tile's PV ----
    {
        const float* Vl = smem + ((nkt + 2) % 3)*STAGEF + 64*KLD;  // (nkt-1)%3
        #pragma unroll
        for (int n = 0; n < 12; n++) {
            o[n][0]*=fp_lo; o[n][1]*=fp_lo; o[n][2]*=fp_hi; o[n][3]*=fp_hi;
        }
        #pragma unroll
        for (int j = 0; j < 8; j++) {
            #pragma unroll
            for (int n = 0; n < 12; n++) {
                uint32_t b0 = __float_as_uint(Vl[(j*8 + t)*VLD + n*8 + g]);
                uint32_t b1 = __float_as_uint(Vl[(j*8 + t + 4)*VLD + n*8 + g]);
                mma8(o[n], pa[j][0],pa[j][1],pa[j][2],pa[j][3], b0,b1);
            }
        }
    }

    // ---- normalize and store ----
    const float ilo = 1.0f / l_lo;
    const float ihi = 1.0f / l_hi;
    const int orow = rq0 + w*16 + g;
    #pragma unroll
    for (int n = 0; n < 12; n++) {
        float2 lo = make_float2(o[n][0]*ilo, o[n][1]*ilo);
        float2 hi = make_float2(o[n][2]*ihi, o[n][3]*ihi);
        *reinterpret_cast<float2*>(&out[(size_t)orow*H_ + n*8 + 2*t]) = lo;
        *reinterpret_cast<float2*>(&out[(size_t)(orow+8)*H_ + n*8 + 2*t]) = hi;
    }
}

// ----------------------------- Launch -----------------------------
extern "C" void kernel_launch(void* const* d_in, const int* in_sizes, int n_in,
                              void* d_out, int out_size)
{
    const float* x  = (const float*)d_in[0];
    const float* Wq = (const float*)d_in[1];
    const float* Wk = (const float*)d_in[2];
    const float* Wv = (const float*)d_in[3];
    float* out = (float*)d_out;

    cudaFuncSetAttribute(qkv_kernel, cudaFuncAttributeMaxDynamicSharedMemorySize,
                         QKV_SMEM_BYTES);
    cudaFuncSetAttribute(attn_kernel, cudaFuncAttributeMaxDynamicSharedMemorySize,
                         ATTN_SMEM_BYTES);

    dim3 g1(M_/128, 3);
    qkv_kernel<<<g1, 128, QKV_SMEM_BYTES>>>(x, Wq, Wk, Wv);

    dim3 g2(S_/128, B_);
    attn_kernel<<<g2, 256, ATTN_SMEM_BYTES>>>(out);
}

// round 16
// speedup vs baseline: 1.2668x; 1.0053x over previous
#include <cuda_runtime.h>
#include <cstdint>

#define B_ 16
#define S_ 2048
#define E_ 768
#define H_ 96
#define M_ (B_*S_)

// Scratch: q (pre-scaled, tf32-rounded), k, v (tf32-rounded, row-major)
__device__ float g_q[M_*H_];
__device__ float g_k[M_*H_];
__device__ float g_v[M_*H_];

#define SCALE_ 0.1020620726159658f   // 96^-0.5

__device__ __forceinline__ float to_tf32(float x)
{
    asm("cvt.rna.tf32.f32 %0, %1;" : "=f"(x) : "f"(x));
    return x;
}

// NOT volatile: data deps via operands are sufficient; lets ptxas interleave
// MMAs with LDS and FP code across accumulators.
__device__ __forceinline__ void mma8(float c[4],
                                     uint32_t a0, uint32_t a1, uint32_t a2, uint32_t a3,
                                     uint32_t b0, uint32_t b1)
{
    asm("mma.sync.aligned.m16n8k8.row.col.f32.tf32.tf32.f32 "
        "{%0,%1,%2,%3}, {%4,%5,%6,%7}, {%8,%9}, {%0,%1,%2,%3};\n"
        : "+f"(c[0]), "+f"(c[1]), "+f"(c[2]), "+f"(c[3])
        : "r"(a0), "r"(a1), "r"(a2), "r"(a3), "r"(b0), "r"(b1));
}

__device__ __forceinline__ void cpa16(uint32_t dst, const float* src)
{
    asm volatile("cp.async.cg.shared.global [%0], [%1], 16;\n" :: "r"(dst), "l"(src) : "memory");
}
__device__ __forceinline__ void cpa_commit() { asm volatile("cp.async.commit_group;\n" ::: "memory"); }
__device__ __forceinline__ void cpa_wait1()  { asm volatile("cp.async.wait_group 1;\n" ::: "memory"); }

// ----------------------------- QKV projection -----------------------------
// Structure unchanged from R15 (passing); mma8 now non-volatile.
#define XLD 36
#define WLD 104
#define QSTAGEF (128*XLD + 32*WLD)        // 7936 floats
#define QKV_SMEM_BYTES (2*QSTAGEF*4)      // 63488 B

__device__ __forceinline__ void qkv_fill(const float* __restrict__ X,
                                         const float* __restrict__ W,
                                         int row0, int kt, uint32_t st_u, int tid)
{
    uint32_t xs_u = st_u;
    uint32_t ws_u = st_u + (uint32_t)(128*XLD)*4;
    #pragma unroll
    for (int i = 0; i < 8; i++) {           // X: 128 rows x 8 float4 = 1024
        int idx = tid + i*128;
        int r = idx >> 3, c = idx & 7;
        cpa16(xs_u + (uint32_t)(r*XLD + c*4)*4,
              &X[(size_t)(row0 + r)*E_ + kt*32 + c*4]);
    }
    #pragma unroll
    for (int i = 0; i < 6; i++) {           // W: 32 rows x 24 float4 = 768
        int idx = tid + i*128;
        int r = idx / 24, c = idx - r*24;
        cpa16(ws_u + (uint32_t)(r*WLD + c*4)*4,
              &W[(size_t)(kt*32 + r)*H_ + c*4]);
    }
}

__global__ __launch_bounds__(128, 3) void qkv_kernel(
    const float* __restrict__ X,
    const float* __restrict__ Wq,
    const float* __restrict__ Wk,
    const float* __restrict__ Wv)
{
    extern __shared__ float qs[];
    const int tid  = threadIdx.x;
    const int w    = tid >> 5;
    const int lane = tid & 31;
    const int g    = lane >> 2;
    const int t    = lane & 3;
    const int row0 = blockIdx.x * 128;
    const int y    = blockIdx.y;

    const float* W = (y == 0) ? Wq : (y == 1) ? Wk : Wv;
    float* Out     = (y == 0) ? g_q : (y == 1) ? g_k : g_v;
    const float sc = (y == 0) ? SCALE_ : 1.0f;

    const uint32_t smem_u = (uint32_t)__cvta_generic_to_shared(qs);

    float o[2][12][4];
    #pragma unroll
    for (int r = 0; r < 2; r++)
        #pragma unroll
        for (int n = 0; n < 12; n++)
            o[r][n][0] = o[r][n][1] = o[r][n][2] = o[r][n][3] = 0.0f;

    qkv_fill(X, W, row0, 0, smem_u, tid);
    cpa_commit();

    for (int kt = 0; kt < 24; kt++) {
        if (kt + 1 < 24)
            qkv_fill(X, W, row0, kt + 1, smem_u + (uint32_t)(((kt+1)&1)*QSTAGEF)*4, tid);
        cpa_commit();
        cpa_wait1();
        __syncthreads();

        const float* Xs = qs + (kt & 1)*QSTAGEF;
        const float* Ws = Xs + 128*XLD;

        #pragma unroll
        for (int kc = 0; kc < 4; kc++) {
            uint32_t a[2][4];
            #pragma unroll
            for (int rt = 0; rt < 2; rt++) {
                int rr = w*32 + rt*16 + g;
                a[rt][0] = __float_as_uint(to_tf32(Xs[rr*XLD + kc*8 + t]));
                a[rt][1] = __float_as_uint(to_tf32(Xs[(rr+8)*XLD + kc*8 + t]));
                a[rt][2] = __float_as_uint(to_tf32(Xs[rr*XLD + kc*8 + t + 4]));
                a[rt][3] = __float_as_uint(to_tf32(Xs[(rr+8)*XLD + kc*8 + t + 4]));
            }
            #pragma unroll
            for (int n = 0; n < 12; n++) {
                uint32_t b0 = __float_as_uint(to_tf32(Ws[(kc*8 + t)*WLD + n*8 + g]));
                uint32_t b1 = __float_as_uint(to_tf32(Ws[(kc*8 + t + 4)*WLD + n*8 + g]));
                mma8(o[0][n], a[0][0],a[0][1],a[0][2],a[0][3], b0,b1);
                mma8(o[1][n], a[1][0],a[1][1],a[1][2],a[1][3], b0,b1);
            }
        }
        __syncthreads();
    }

    #pragma unroll
    for (int rt = 0; rt < 2; rt++) {
        int rr = row0 + w*32 + rt*16 + g;
        #pragma unroll
        for (int n = 0; n < 12; n++) {
            float2 lo = make_float2(to_tf32(o[rt][n][0]*sc), to_tf32(o[rt][n][1]*sc));
            float2 hi = make_float2(to_tf32(o[rt][n][2]*sc), to_tf32(o[rt][n][3]*sc));
            *reinterpret_cast<float2*>(&Out[(size_t)rr*H_ + n*8 + 2*t]) = lo;
            *reinterpret_cast<float2*>(&Out[(size_t)(rr+8)*H_ + n*8 + 2*t]) = hi;
        }
    }
}

// ----------------------------- Attention -----------------------------
// Cross-tile pipelined flash (R15 structure). Deltas: non-volatile mma,
// S-gemm loop order kc-outer/j-inner (8 independent accumulators in flight).
#define KLD 100
#define VLD 104
#define STAGEF (64*KLD + 64*VLD)          // 13056 floats
#define ATTN_SMEM_BYTES (3*STAGEF*4)      // 156672 B

__device__ __forceinline__ void attn_fill(int b, int kt, uint32_t st_u, int tid)
{
    uint32_t ks_u = st_u;
    uint32_t vs_u = st_u + (uint32_t)(64*KLD)*4;
    #pragma unroll
    for (int i = 0; i < 6; i++) {           // 64 rows x 24 float4 = 1536
        int idx = tid + i*256;
        int r = idx / 24, c = idx - r*24;
        size_t gb = (size_t)(b*S_ + kt*64 + r)*H_ + c*4;
        cpa16(ks_u + (uint32_t)(r*KLD + c*4)*4, &g_k[gb]);
        cpa16(vs_u + (uint32_t)(r*VLD + c*4)*4, &g_v[gb]);
    }
}

// P accum-layout -> A-fragment layout via shfl (proven in R6/R10)
__device__ __forceinline__ void p_to_afrag(const float s[4], uint32_t pa[4],
                                           int src, bool odd)
{
    float v0 = __shfl_sync(0xffffffffu, s[0], src);
    float v1 = __shfl_sync(0xffffffffu, s[1], src);
    float v2 = __shfl_sync(0xffffffffu, s[2], src);
    float v3 = __shfl_sync(0xffffffffu, s[3], src);
    float u0 = __shfl_sync(0xffffffffu, s[0], src + 2);
    float u1 = __shfl_sync(0xffffffffu, s[1], src + 2);
    float u2 = __shfl_sync(0xffffffffu, s[2], src + 2);
    float u3 = __shfl_sync(0xffffffffu, s[3], src + 2);
    pa[0] = __float_as_uint(odd ? v1 : v0);
    pa[1] = __float_as_uint(odd ? v3 : v2);
    pa[2] = __float_as_uint(odd ? u1 : u0);
    pa[3] = __float_as_uint(odd ? u3 : u2);
}

__global__ __launch_bounds__(256) void attn_kernel(float* __restrict__ out)
{
    extern __shared__ float smem[];
    const int tid  = threadIdx.x;
    const int w    = tid >> 5;
    const int lane = tid & 31;
    const int g    = lane >> 2;
    const int t    = lane & 3;
    const int qt   = (S_/128 - 1) - blockIdx.x;   // big CTAs first
    const int b    = blockIdx.y;
    const int rq0  = b*S_ + qt*128;

    const uint32_t smem_u = (uint32_t)__cvta_generic_to_shared(smem);

    // Zero V region of stage 2 (read by the branchless kt=0 pipelined PV)
    {
        float* vz = smem + 2*STAGEF + 64*KLD;
        for (int i = tid; i < 64*VLD; i += 256) vz[i] = 0.0f;
    }

    // Q fragments straight from gmem (pre-scaled, pre-rounded, L2-resident)
    uint32_t qa[12][4];
    {
        const size_t qr0 = (size_t)(rq0 + w*16 + g)*H_;
        const size_t qr8 = qr0 + 8*H_;
        #pragma unroll
        for (int kc = 0; kc < 12; kc++) {
            qa[kc][0] = __float_as_uint(g_q[qr0 + kc*8 + t]);
            qa[kc][1] = __float_as_uint(g_q[qr8 + kc*8 + t]);
            qa[kc][2] = __float_as_uint(g_q[qr0 + kc*8 + t + 4]);
            qa[kc][3] = __float_as_uint(g_q[qr8 + kc*8 + t + 4]);
        }
    }

    float o[12][4];
    uint32_t pa[8][4];
    #pragma unroll
    for (int n = 0; n < 12; n++)
        o[n][0] = o[n][1] = o[n][2] = o[n][3] = 0.0f;
    #pragma unroll
    for (int j = 0; j < 8; j++)
        pa[j][0] = pa[j][1] = pa[j][2] = pa[j][3] = 0;   // 0.0f bit pattern

    float m_lo = -1e30f, m_hi = -1e30f, l_lo = 0.0f, l_hi = 0.0f;
    float fp_lo = 1.0f, fp_hi = 1.0f;     // saved rescale factors of prev tile
    const int rlo = qt*128 + w*16 + g;
    const int rhi = rlo + 8;
    const int nkt = 2*qt + 2;
    const int src = (g << 2) + (t >> 1);
    const bool odd = (t & 1);

    attn_fill(b, 0, smem_u, tid);
    cpa_commit();

    for (int kt = 0; kt < nkt; kt++) {
        if (kt + 1 < nkt)
            attn_fill(b, kt + 1, smem_u + (uint32_t)(((kt+1)%3)*STAGEF)*4, tid);
        cpa_commit();
        cpa_wait1();
        __syncthreads();

        const float* Ks = smem + (kt % 3)*STAGEF;
        const float* Vp = smem + ((kt + 2) % 3)*STAGEF + 64*KLD;  // V of tile kt-1

        // ---- S = Qscaled @ K^T : kc outer, j inner (8 indep accumulators) ----
        float s[8][4];
        #pragma unroll
        for (int j = 0; j < 8; j++) {
            s[j][0]=s[j][1]=s[j][2]=s[j][3]=0.0f;
        }
        #pragma unroll
        for (int kc = 0; kc < 12; kc++) {
            #pragma unroll
            for (int j = 0; j < 8; j++) {
                uint32_t b0 = __float_as_uint(Ks[(j*8+g)*KLD + kc*8 + t]);
                uint32_t b1 = __float_as_uint(Ks[(j*8+g)*KLD + kc*8 + t + 4]);
                mma8(s[j], qa[kc][0],qa[kc][1],qa[kc][2],qa[kc][3], b0,b1);
            }
        }

        // ---- causal mask (near diagonal only) ----
        if (kt*64 + 63 > rlo) {
            #pragma unroll
            for (int j = 0; j < 8; j++) {
                int c0 = kt*64 + j*8 + 2*t;
                if (c0     > rlo) s[j][0] = -1e30f;
                if (c0 + 1 > rlo) s[j][1] = -1e30f;
                if (c0     > rhi) s[j][2] = -1e30f;
                if (c0 + 1 > rhi) s[j][3] = -1e30f;
            }
        }

        // ---- row-max reduction (current tile) ----
        float pm_lo = -1e30f, pm_hi = -1e30f;
        #pragma unroll
        for (int j = 0; j < 8; j++) {
            pm_lo = fmaxf(pm_lo, fmaxf(s[j][0], s[j][1]));
            pm_hi = fmaxf(pm_hi, fmaxf(s[j][2], s[j][3]));
        }
        pm_lo = fmaxf(pm_lo, __shfl_xor_sync(0xffffffffu, pm_lo, 1));
        pm_lo = fmaxf(pm_lo, __shfl_xor_sync(0xffffffffu, pm_lo, 2));
        pm_hi = fmaxf(pm_hi, __shfl_xor_sync(0xffffffffu, pm_hi, 1));
        pm_hi = fmaxf(pm_hi, __shfl_xor_sync(0xffffffffu, pm_hi, 2));

        float mlo_n = fmaxf(m_lo, pm_lo);
        float mhi_n = fmaxf(m_hi, pm_hi);
        float flo = __expf(m_lo - mlo_n);
        float fhi = __expf(m_hi - mhi_n);
        m_lo = mlo_n; m_hi = mhi_n;

        // ---- PIPELINED O update for PREVIOUS tile (overlaps softmax below) ----
        #pragma unroll
        for (int n = 0; n < 12; n++) {
            o[n][0]*=fp_lo; o[n][1]*=fp_lo; o[n][2]*=fp_hi; o[n][3]*=fp_hi;
        }
        #pragma unroll
        for (int j = 0; j < 8; j++) {
            #pragma unroll
            for (int n = 0; n < 12; n++) {
                uint32_t b0 = __float_as_uint(Vp[(j*8 + t)*VLD + n*8 + g]);
                uint32_t b1 = __float_as_uint(Vp[(j*8 + t + 4)*VLD + n*8 + g]);
                mma8(o[n], pa[j][0],pa[j][1],pa[j][2],pa[j][3], b0,b1);
            }
        }

        // ---- exp + denominator (current tile) ----
        float slo = 0.0f, shi = 0.0f;
        #pragma unroll
        for (int j = 0; j < 8; j++) {
            s[j][0] = __expf(s[j][0] - mlo_n); slo += s[j][0];
            s[j][1] = __expf(s[j][1] - mlo_n); slo += s[j][1];
            s[j][2] = __expf(s[j][2] - mhi_n); shi += s[j][2];
            s[j][3] = __expf(s[j][3] - mhi_n); shi += s[j][3];
        }
        slo += __shfl_xor_sync(0xffffffffu, slo, 1);
        slo += __shfl_xor_sync(0xffffffffu, slo, 2);
        shi += __shfl_xor_sync(0xffffffffu, shi, 1);
        shi += __shfl_xor_sync(0xffffffffu, shi, 2);
        l_lo = l_lo*flo + slo;
        l_hi = l_hi*fhi + shi;

        // ---- round P to tf32 and convert to A-fragments for NEXT iteration ----
        #pragma unroll
        for (int j = 0; j < 8; j++) {
            s[j][0] = to_tf32(s[j][0]);
            s[j][1] = to_tf32(s[j][1]);
            s[j][2] = to_tf32(s[j][2]);
            s[j][3] = to_tf32(s[j][3]);
            p_to_afrag(s[j], pa[j], src, odd);
        }
        fp_lo = flo; fp_hi = fhi;

        __syncthreads();   // all reads of stages kt%3 and (kt-1)%3 done
    }

    // ---- epilogue: fold in the last tile's PV ----
    {
        const float* Vl = smem + ((nkt + 2) % 3)*STAGEF + 64*KLD;  // (nkt-1)%3
        #pragma unroll
        for (int n = 0; n < 12; n++) {
            o[n][0]*=fp_lo; o[n][1]*=fp_lo; o[n][2]*=fp_hi; o[n][3]*=fp_hi;
        }
        #pragma unroll
        for (int j = 0; j < 8; j++) {
            #pragma unroll
            for (int n = 0; n < 12; n++) {
                uint32_t b0 = __float_as_uint(Vl[(j*8 + t)*VLD + n*8 + g]);
                uint32_t b1 = __float_as_uint(Vl[(j*8 + t + 4)*VLD + n*8 + g]);
                mma8(o[n], pa[j][0],pa[j][1],pa[j][2],pa[j][3], b0,b1);
            }
        }
    }

    // ---- normalize and store ----
    const float ilo = 1.0f / l_lo;
    const float ihi = 1.0f / l_hi;
    const int orow = rq0 + w*16 + g;
    #pragma unroll
    for (int n = 0; n < 12; n++) {
        float2 lo = make_float2(o[n][0]*ilo, o[n][1]*ilo);
        float2 hi = make_float2(o[n][2]*ihi, o[n][3]*ihi);
        *reinterpret_cast<float2*>(&out[(size_t)orow*H_ + n*8 + 2*t]) = lo;
        *reinterpret_cast<float2*>(&out[(size_t)(orow+8)*H_ + n*8 + 2*t]) = hi;
    }
}

// ----------------------------- Launch -----------------------------
extern "C" void kernel_launch(void* const* d_in, const int* in_sizes, int n_in,
                              void* d_out, int out_size)
{
    const float* x  = (const float*)d_in[0];
    const float* Wq = (const float*)d_in[1];
    const float* Wk = (const float*)d_in[2];
    const float* Wv = (const float*)d_in[3];
    float* out = (float*)d_out;

    cudaFuncSetAttribute(qkv_kernel, cudaFuncAttributeMaxDynamicSharedMemorySize,
                         QKV_SMEM_BYTES);
    cudaFuncSetAttribute(attn_kernel, cudaFuncAttributeMaxDynamicSharedMemorySize,
                         ATTN_SMEM_BYTES);

    dim3 g1(M_/128, 3);
    qkv_kernel<<<g1, 128, QKV_SMEM_BYTES>>>(x, Wq, Wk, Wv);

    dim3 g2(S_/128, B_);
    attn_kernel<<<g2, 256, ATTN_SMEM_BYTES>>>(out);
}